// round 2
// baseline (speedup 1.0000x reference)
#include <cuda_runtime.h>

#define TK      2048
#define NCH     64
#define CL      32
#define NTHR    256
#define NEGV    (-1.0e4f)
#define NEGINF  (-1.0e30f)
#define NITER   6

// XOR swizzle so chunk-strided smem access (stride 32 floats) is bank-conflict-free.
__device__ __forceinline__ int SW(int t) { return t ^ ((t >> 5) & 31); }

// Dynamic smem layout (bytes):
//     0: float4 alphas[2048]        32768
// 32768: float2 gpgm[2048]          16384
// 49152: float  ys1[2048]            8192
// 57344: float  yp2[2048]            8192
// 65536: float  yp3[2048]            8192
// 73728: float  apri1[2048]          8192
// 81920: float  apri2[2048]          8192
// 90112: float  Mf[64*16]            4096
// 94208: float  Mb[64*16]            4096
// 98304: float  bndA[65*4]           1040
// 99344: float  bndB[65*4]           1040
//100384: u16    ilv[2048]            4096
//104480: u16    inv[2048]            4096
//108576: u8     xb[2048]             2048
//110624: u8     emap[2*64]            128
//110752: u8     est[2*65]             130
// total 110882 -> 110912
#define SMEM_BYTES 110912

extern "C" __global__ void __launch_bounds__(NTHR, 2)
turbo_full_kernel(const int* __restrict__ x_g,
                  const float* __restrict__ n1_g,
                  const float* __restrict__ n2_g,
                  const float* __restrict__ n3_g,
                  const int* __restrict__ ilv_g,
                  float* __restrict__ out_g)
{
    extern __shared__ unsigned char sm[];
    float4* alphas = (float4*)(sm + 0);
    float2* gpgm   = (float2*)(sm + 32768);
    float*  ys1    = (float*)(sm + 49152);
    float*  yp2    = (float*)(sm + 57344);
    float*  yp3    = (float*)(sm + 65536);
    float*  apri1  = (float*)(sm + 73728);
    float*  apri2  = (float*)(sm + 81920);
    float*  Mf     = (float*)(sm + 90112);
    float*  Mb     = (float*)(sm + 94208);
    float*  bndA   = (float*)(sm + 98304);
    float*  bndB   = (float*)(sm + 99344);
    unsigned short* ilv = (unsigned short*)(sm + 100384);
    unsigned short* inv = (unsigned short*)(sm + 104480);
    unsigned char*  xb  = (unsigned char*)(sm + 108576);
    unsigned char*  emap= (unsigned char*)(sm + 110624);
    unsigned char*  est = (unsigned char*)(sm + 110752);

    const int row = blockIdx.x;
    const int tid = threadIdx.x;

    const int*   xr  = x_g  + (size_t)row * TK;
    const float* n1r = n1_g + (size_t)row * TK;
    const float* n2r = n2_g + (size_t)row * TK;
    const float* n3r = n3_g + (size_t)row * TK;
    float*       outr= out_g+ (size_t)row * TK;

    // ---------------- Prologue: load, BPSK, noise ----------------
    #pragma unroll
    for (int t = tid; t < TK; t += NTHR) {
        int il = ilv_g[t];
        ilv[t] = (unsigned short)il;
        int u = xr[t];
        xb[t] = (unsigned char)u;
        ys1[t]   = (2.0f * (float)u - 1.0f) + n1r[t];   // y1 (systematic)
        yp2[t]   = n2r[t];                              // parity1 BPSK added later
        yp3[t]   = n3r[t];                              // parity2 BPSK added later
        apri1[t] = 0.0f;
    }
    __syncthreads();
    #pragma unroll
    for (int t = tid; t < TK; t += NTHR) inv[ilv[t]] = (unsigned short)t;

    // ---------------- Encoders (chunked state-map scan) ----------------
    // Phase E1: per-chunk 4->4 state map, packed 2 bits/state in a byte.
    if (tid < 128) {
        int e = tid >> 6;      // 0: encoder1 (x), 1: encoder2 (x interleaved)
        int c = tid & 63;
        unsigned m = 0xE4u;    // identity map: state k -> k
        int base = c * CL;
        for (int i = 0; i < CL; i++) {
            int t = base + i;
            unsigned u = e ? xb[ilv[t]] : xb[t];
            unsigned nm = 0;
            #pragma unroll
            for (int k = 0; k < 4; k++) {
                unsigned s  = (m >> (2 * k)) & 3u;
                unsigned s1 = s >> 1, s2 = s & 1u;
                unsigned a  = u ^ s1 ^ s2;
                nm |= (((a << 1) | s1) << (2 * k));
            }
            m = nm;
        }
        emap[e * 64 + c] = (unsigned char)m;
    }
    __syncthreads();
    // Phase E2: boundary-state scan (two threads, different warps)
    if (tid == 0 || tid == 32) {
        int e = (tid == 32) ? 1 : 0;
        unsigned s = 0;
        for (int c = 0; c < NCH; c++) {
            est[e * 65 + c] = (unsigned char)s;
            s = (emap[e * 64 + c] >> (2 * s)) & 3u;
        }
        est[e * 65 + 64] = (unsigned char)s;
    }
    __syncthreads();
    // Phase E3: replay chunks, emit parity BPSK into yp2/yp3
    if (tid < 128) {
        int e = tid >> 6;
        int c = tid & 63;
        unsigned s = est[e * 65 + c];
        int base = c * CL;
        for (int i = 0; i < CL; i++) {
            int t = base + i;
            unsigned u  = e ? xb[ilv[t]] : xb[t];
            unsigned s1 = s >> 1, s2 = s & 1u;
            unsigned a  = u ^ s1 ^ s2;
            unsigned p  = a ^ s2;
            float bp = 2.0f * (float)p - 1.0f;
            if (e) yp3[t] += bp; else yp2[t] += bp;
            s = (a << 1) | s1;
        }
    }
    __syncthreads();

    // ---------------- Turbo iterations ----------------
    for (int it = 0; it < NITER; it++) {
        for (int dec = 0; dec < 2; dec++) {
            // ---- Gamma: gp = ys + La/2 + yp, gm = ys + La/2 - yp (Lc=2) ----
            #pragma unroll
            for (int t = tid; t < TK; t += NTHR) {
                float a, b;
                if (dec == 0) { a = ys1[t]      + 0.5f * apri1[t]; b = yp2[t]; }
                else          { a = ys1[ilv[t]] + 0.5f * apri2[t]; b = yp3[t]; }
                gpgm[SW(t)] = make_float2(a + b, a - b);
            }
            __syncthreads();

            // ---- Phase 1: per-chunk 4x4 transfer matrices (fwd + bwd) ----
            {
                int c = tid >> 2, j = tid & 3;
                int base = c * CL;
                float a0 = (j == 0) ? 0.0f : NEGINF;
                float a1 = (j == 1) ? 0.0f : NEGINF;
                float a2 = (j == 2) ? 0.0f : NEGINF;
                float a3 = (j == 3) ? 0.0f : NEGINF;
                #pragma unroll 4
                for (int i = 0; i < CL; i++) {
                    float2 g = gpgm[SW(base + i)];
                    float gp = g.x, gm = g.y;
                    float m0 = fmaxf(a0 - gp, a1 + gp);
                    float m2 = fmaxf(a0 + gp, a1 - gp);
                    float m1 = fmaxf(a2 + gm, a3 - gm);
                    float m3 = fmaxf(a2 - gm, a3 + gm);
                    a0 = m0; a1 = m1; a2 = m2; a3 = m3;
                }
                float* M = Mf + c * 16 + j * 4;
                M[0] = a0; M[1] = a1; M[2] = a2; M[3] = a3;

                float b0 = (j == 0) ? 0.0f : NEGINF;
                float b1 = (j == 1) ? 0.0f : NEGINF;
                float b2 = (j == 2) ? 0.0f : NEGINF;
                float b3 = (j == 3) ? 0.0f : NEGINF;
                #pragma unroll 4
                for (int i = CL - 1; i >= 0; i--) {
                    float2 g = gpgm[SW(base + i)];
                    float gp = g.x, gm = g.y;
                    float m0 = fmaxf(b0 - gp, b2 + gp);
                    float m1 = fmaxf(b2 - gp, b0 + gp);
                    float m2 = fmaxf(b3 - gm, b1 + gm);
                    float m3 = fmaxf(b1 - gm, b3 + gm);
                    b0 = m0; b1 = m1; b2 = m2; b3 = m3;
                }
                float* Mp = Mb + c * 16 + j * 4;
                Mp[0] = b0; Mp[1] = b1; Mp[2] = b2; Mp[3] = b3;
            }
            __syncthreads();

            // ---- Phase 2: serial matrix-vector scans (two warps concurrent) ----
            if (tid == 0) {
                float v0 = 0.0f, v1 = NEGV, v2 = NEGV, v3 = NEGV;
                bndA[0] = v0; bndA[1] = v1; bndA[2] = v2; bndA[3] = v3;
                for (int c = 0; c < NCH; c++) {
                    const float* M = Mf + c * 16;
                    float w0 = fmaxf(fmaxf(M[0] + v0, M[4] + v1), fmaxf(M[8]  + v2, M[12] + v3));
                    float w1 = fmaxf(fmaxf(M[1] + v0, M[5] + v1), fmaxf(M[9]  + v2, M[13] + v3));
                    float w2 = fmaxf(fmaxf(M[2] + v0, M[6] + v1), fmaxf(M[10] + v2, M[14] + v3));
                    float w3 = fmaxf(fmaxf(M[3] + v0, M[7] + v1), fmaxf(M[11] + v2, M[15] + v3));
                    v0 = 0.0f; v1 = w1 - w0; v2 = w2 - w0; v3 = w3 - w0;
                    float* bp = bndA + (c + 1) * 4;
                    bp[0] = v0; bp[1] = v1; bp[2] = v2; bp[3] = v3;
                }
            } else if (tid == 32) {
                float v0 = 0.0f, v1 = 0.0f, v2 = 0.0f, v3 = 0.0f;
                float* bp64 = bndB + NCH * 4;
                bp64[0] = 0.0f; bp64[1] = 0.0f; bp64[2] = 0.0f; bp64[3] = 0.0f;
                for (int c = NCH - 1; c >= 0; c--) {
                    const float* M = Mb + c * 16;
                    float w0 = fmaxf(fmaxf(M[0] + v0, M[4] + v1), fmaxf(M[8]  + v2, M[12] + v3));
                    float w1 = fmaxf(fmaxf(M[1] + v0, M[5] + v1), fmaxf(M[9]  + v2, M[13] + v3));
                    float w2 = fmaxf(fmaxf(M[2] + v0, M[6] + v1), fmaxf(M[10] + v2, M[14] + v3));
                    float w3 = fmaxf(fmaxf(M[3] + v0, M[7] + v1), fmaxf(M[11] + v2, M[15] + v3));
                    v0 = 0.0f; v1 = w1 - w0; v2 = w2 - w0; v3 = w3 - w0;
                    float* bp = bndB + c * 4;
                    bp[0] = v0; bp[1] = v1; bp[2] = v2; bp[3] = v3;
                }
            }
            __syncthreads();

            // ---- Phase 3a: forward replay, store alphas (pre-step, like ref) ----
            if (tid < NCH) {
                int c = tid;
                const float* bp = bndA + c * 4;
                float a0 = bp[0], a1 = bp[1], a2 = bp[2], a3 = bp[3];
                int base = c * CL;
                #pragma unroll 4
                for (int i = 0; i < CL; i++) {
                    int ts = SW(base + i);
                    alphas[ts] = make_float4(a0, a1, a2, a3);
                    float2 g = gpgm[ts];
                    float gp = g.x, gm = g.y;
                    float m0 = fmaxf(a0 - gp, a1 + gp);
                    float m2 = fmaxf(a0 + gp, a1 - gp);
                    float m1 = fmaxf(a2 + gm, a3 - gm);
                    float m3 = fmaxf(a2 - gm, a3 + gm);
                    a0 = m0; a1 = m1; a2 = m2; a3 = m3;
                }
            }
            __syncthreads();

            // ---- Phase 3b: backward replay + LLR + extrinsic scatter ----
            if (tid < NCH) {
                int c = tid;
                const float* bp = bndB + (c + 1) * 4;
                float b0 = bp[0], b1 = bp[1], b2 = bp[2], b3 = bp[3];
                int base = c * CL;
                #pragma unroll 2
                for (int i = CL - 1; i >= 0; i--) {
                    int t  = base + i;
                    int ts = SW(t);
                    float2 g = gpgm[ts];
                    float gp = g.x, gm = g.y;
                    float4 al = alphas[ts];
                    float t0p = b2 + gp, t1p = b0 + gp, t2p = b1 + gm, t3p = b3 + gm;
                    float t0m = b0 - gp, t1m = b2 - gp, t2m = b3 - gm, t3m = b1 - gm;
                    float m1v = fmaxf(fmaxf(al.x + t0p, al.y + t1p),
                                      fmaxf(al.z + t2p, al.w + t3p));
                    float m0v = fmaxf(fmaxf(al.x + t0m, al.y + t1m),
                                      fmaxf(al.z + t2m, al.w + t3m));
                    float llr = m1v - m0v;
                    b0 = fmaxf(t0m, t0p);
                    b1 = fmaxf(t1m, t1p);
                    b2 = fmaxf(t2m, t2p);
                    b3 = fmaxf(t3m, t3p);
                    if (dec == 0) {
                        // Le1 interleaved -> apriori of decoder 2
                        apri2[inv[t]] = llr - 2.0f * ys1[t] - apri1[t];
                    } else {
                        int il = ilv[t];
                        // Le2 deinterleaved -> apriori of decoder 1
                        apri1[il] = llr - 2.0f * ys1[il] - apri2[t];
                        if (it == NITER - 1) outr[il] = llr;  // final deinterleaved L2
                    }
                }
            }
            __syncthreads();
        }
    }
}

extern "C" void kernel_launch(void* const* d_in, const int* in_sizes, int n_in,
                              void* d_out, int out_size)
{
    const int*   x  = (const int*)d_in[0];
    const float* n1 = (const float*)d_in[1];
    const float* n2 = (const float*)d_in[2];
    const float* n3 = (const float*)d_in[3];
    const int*   il = (const int*)d_in[4];
    float* out = (float*)d_out;

    int B = in_sizes[0] / TK;

    cudaFuncSetAttribute(turbo_full_kernel,
                         cudaFuncAttributeMaxDynamicSharedMemorySize, SMEM_BYTES);
    turbo_full_kernel<<<B, NTHR, SMEM_BYTES>>>(x, n1, n2, n3, il, out);
}

// round 3
// speedup vs baseline: 1.0010x; 1.0010x over previous
#include <cuda_runtime.h>

#define TK      2048
#define NCH     64
#define CL      32
#define NTHR    256
#define NEGV    (-1.0e4f)
#define NEGINF  (-1.0e30f)
#define NITER   6

// XOR swizzle so chunk-strided smem access (stride 32 floats) is bank-conflict-free.
__device__ __forceinline__ int SW(int t) { return t ^ ((t >> 5) & 31); }

// Dynamic smem layout (bytes):
//     0: float4 alphas[2048]        32768
// 32768: float2 gpgm[2048]          16384
// 49152: float  ys1[2048]            8192
// 57344: float  yp2[2048]            8192
// 65536: float  yp3[2048]            8192
// 73728: float  apri1[2048]          8192
// 81920: float  apri2[2048]          8192
// 90112: float  Mf[64*16]            4096
// 94208: float  Mb[64*16]            4096
// 98304: float  bndA[65*4]           1040
// 99344: float  bndB[65*4]           1040
//100384: u16    ilv[2048]            4096
//104480: u16    inv[2048]            4096
//108576: u8     xb[2048]             2048
//110624: u8     emap[2*64]            128
//110752: u8     est[2*65]             130
// total 110882 -> 110912
#define SMEM_BYTES 110912

extern "C" __global__ void __launch_bounds__(NTHR, 2)
turbo_full_kernel(const int* __restrict__ x_g,
                  const float* __restrict__ n1_g,
                  const float* __restrict__ n2_g,
                  const float* __restrict__ n3_g,
                  const int* __restrict__ ilv_g,
                  float* __restrict__ out_g)
{
    extern __shared__ unsigned char sm[];
    float4* alphas = (float4*)(sm + 0);
    float2* gpgm   = (float2*)(sm + 32768);
    float*  ys1    = (float*)(sm + 49152);
    float*  yp2    = (float*)(sm + 57344);
    float*  yp3    = (float*)(sm + 65536);
    float*  apri1  = (float*)(sm + 73728);
    float*  apri2  = (float*)(sm + 81920);
    float*  Mf     = (float*)(sm + 90112);
    float*  Mb     = (float*)(sm + 94208);
    float*  bndA   = (float*)(sm + 98304);
    float*  bndB   = (float*)(sm + 99344);
    unsigned short* ilv = (unsigned short*)(sm + 100384);
    unsigned short* inv = (unsigned short*)(sm + 104480);
    unsigned char*  xb  = (unsigned char*)(sm + 108576);
    unsigned char*  emap= (unsigned char*)(sm + 110624);
    unsigned char*  est = (unsigned char*)(sm + 110752);

    const int row = blockIdx.x;
    const int tid = threadIdx.x;

    const int*   xr  = x_g  + (size_t)row * TK;
    const float* n1r = n1_g + (size_t)row * TK;
    const float* n2r = n2_g + (size_t)row * TK;
    const float* n3r = n3_g + (size_t)row * TK;
    float*       outr= out_g+ (size_t)row * TK;

    // ---------------- Prologue: load, BPSK, noise ----------------
    #pragma unroll
    for (int t = tid; t < TK; t += NTHR) {
        int il = ilv_g[t];
        ilv[t] = (unsigned short)il;
        int u = xr[t];
        xb[t] = (unsigned char)u;
        ys1[t]   = (2.0f * (float)u - 1.0f) + n1r[t];   // y1 (systematic)
        yp2[t]   = n2r[t];                              // parity1 BPSK added later
        yp3[t]   = n3r[t];                              // parity2 BPSK added later
        apri1[t] = 0.0f;
    }
    __syncthreads();
    #pragma unroll
    for (int t = tid; t < TK; t += NTHR) inv[ilv[t]] = (unsigned short)t;

    // ---------------- Encoders (chunked state-map scan) ----------------
    // Phase E1: per-chunk 4->4 state map, packed 2 bits/state in a byte.
    if (tid < 128) {
        int e = tid >> 6;      // 0: encoder1 (x), 1: encoder2 (x interleaved)
        int c = tid & 63;
        unsigned m = 0xE4u;    // identity map: state k -> k
        int base = c * CL;
        for (int i = 0; i < CL; i++) {
            int t = base + i;
            unsigned u = e ? xb[ilv[t]] : xb[t];
            unsigned nm = 0;
            #pragma unroll
            for (int k = 0; k < 4; k++) {
                unsigned s  = (m >> (2 * k)) & 3u;
                unsigned s1 = s >> 1, s2 = s & 1u;
                unsigned a  = u ^ s1 ^ s2;
                nm |= (((a << 1) | s1) << (2 * k));
            }
            m = nm;
        }
        emap[e * 64 + c] = (unsigned char)m;
    }
    __syncthreads();
    // Phase E2: boundary-state scan (two threads, different warps)
    if (tid == 0 || tid == 32) {
        int e = (tid == 32) ? 1 : 0;
        unsigned s = 0;
        for (int c = 0; c < NCH; c++) {
            est[e * 65 + c] = (unsigned char)s;
            s = (emap[e * 64 + c] >> (2 * s)) & 3u;
        }
        est[e * 65 + 64] = (unsigned char)s;
    }
    __syncthreads();
    // Phase E3: replay chunks, emit parity BPSK into yp2/yp3
    if (tid < 128) {
        int e = tid >> 6;
        int c = tid & 63;
        unsigned s = est[e * 65 + c];
        int base = c * CL;
        for (int i = 0; i < CL; i++) {
            int t = base + i;
            unsigned u  = e ? xb[ilv[t]] : xb[t];
            unsigned s1 = s >> 1, s2 = s & 1u;
            unsigned a  = u ^ s1 ^ s2;
            unsigned p  = a ^ s2;
            float bp = 2.0f * (float)p - 1.0f;
            if (e) yp3[t] += bp; else yp2[t] += bp;
            s = (a << 1) | s1;
        }
    }
    __syncthreads();

    // ---------------- Turbo iterations ----------------
    for (int it = 0; it < NITER; it++) {
        for (int dec = 0; dec < 2; dec++) {
            // ---- Gamma: gp = ys + La/2 + yp, gm = ys + La/2 - yp (Lc=2) ----
            #pragma unroll
            for (int t = tid; t < TK; t += NTHR) {
                float a, b;
                if (dec == 0) { a = ys1[t]      + 0.5f * apri1[t]; b = yp2[t]; }
                else          { a = ys1[ilv[t]] + 0.5f * apri2[t]; b = yp3[t]; }
                gpgm[SW(t)] = make_float2(a + b, a - b);
            }
            __syncthreads();

            // ---- Phase 1: per-chunk 4x4 transfer matrices (fwd + bwd) ----
            {
                int c = tid >> 2, j = tid & 3;
                int base = c * CL;
                float a0 = (j == 0) ? 0.0f : NEGINF;
                float a1 = (j == 1) ? 0.0f : NEGINF;
                float a2 = (j == 2) ? 0.0f : NEGINF;
                float a3 = (j == 3) ? 0.0f : NEGINF;
                #pragma unroll 4
                for (int i = 0; i < CL; i++) {
                    float2 g = gpgm[SW(base + i)];
                    float gp = g.x, gm = g.y;
                    float m0 = fmaxf(a0 - gp, a1 + gp);
                    float m2 = fmaxf(a0 + gp, a1 - gp);
                    float m1 = fmaxf(a2 + gm, a3 - gm);
                    float m3 = fmaxf(a2 - gm, a3 + gm);
                    a0 = m0; a1 = m1; a2 = m2; a3 = m3;
                }
                float* M = Mf + c * 16 + j * 4;
                M[0] = a0; M[1] = a1; M[2] = a2; M[3] = a3;

                float b0 = (j == 0) ? 0.0f : NEGINF;
                float b1 = (j == 1) ? 0.0f : NEGINF;
                float b2 = (j == 2) ? 0.0f : NEGINF;
                float b3 = (j == 3) ? 0.0f : NEGINF;
                #pragma unroll 4
                for (int i = CL - 1; i >= 0; i--) {
                    float2 g = gpgm[SW(base + i)];
                    float gp = g.x, gm = g.y;
                    float m0 = fmaxf(b0 - gp, b2 + gp);
                    float m1 = fmaxf(b2 - gp, b0 + gp);
                    float m2 = fmaxf(b3 - gm, b1 + gm);
                    float m3 = fmaxf(b1 - gm, b3 + gm);
                    b0 = m0; b1 = m1; b2 = m2; b3 = m3;
                }
                float* Mp = Mb + c * 16 + j * 4;
                Mp[0] = b0; Mp[1] = b1; Mp[2] = b2; Mp[3] = b3;
            }
            __syncthreads();

            // ---- Phase 2: serial matrix-vector scans (two warps concurrent) ----
            if (tid == 0) {
                float v0 = 0.0f, v1 = NEGV, v2 = NEGV, v3 = NEGV;
                bndA[0] = v0; bndA[1] = v1; bndA[2] = v2; bndA[3] = v3;
                for (int c = 0; c < NCH; c++) {
                    const float* M = Mf + c * 16;
                    float w0 = fmaxf(fmaxf(M[0] + v0, M[4] + v1), fmaxf(M[8]  + v2, M[12] + v3));
                    float w1 = fmaxf(fmaxf(M[1] + v0, M[5] + v1), fmaxf(M[9]  + v2, M[13] + v3));
                    float w2 = fmaxf(fmaxf(M[2] + v0, M[6] + v1), fmaxf(M[10] + v2, M[14] + v3));
                    float w3 = fmaxf(fmaxf(M[3] + v0, M[7] + v1), fmaxf(M[11] + v2, M[15] + v3));
                    v0 = 0.0f; v1 = w1 - w0; v2 = w2 - w0; v3 = w3 - w0;
                    float* bp = bndA + (c + 1) * 4;
                    bp[0] = v0; bp[1] = v1; bp[2] = v2; bp[3] = v3;
                }
            } else if (tid == 32) {
                float v0 = 0.0f, v1 = 0.0f, v2 = 0.0f, v3 = 0.0f;
                float* bp64 = bndB + NCH * 4;
                bp64[0] = 0.0f; bp64[1] = 0.0f; bp64[2] = 0.0f; bp64[3] = 0.0f;
                for (int c = NCH - 1; c >= 0; c--) {
                    const float* M = Mb + c * 16;
                    float w0 = fmaxf(fmaxf(M[0] + v0, M[4] + v1), fmaxf(M[8]  + v2, M[12] + v3));
                    float w1 = fmaxf(fmaxf(M[1] + v0, M[5] + v1), fmaxf(M[9]  + v2, M[13] + v3));
                    float w2 = fmaxf(fmaxf(M[2] + v0, M[6] + v1), fmaxf(M[10] + v2, M[14] + v3));
                    float w3 = fmaxf(fmaxf(M[3] + v0, M[7] + v1), fmaxf(M[11] + v2, M[15] + v3));
                    v0 = 0.0f; v1 = w1 - w0; v2 = w2 - w0; v3 = w3 - w0;
                    float* bp = bndB + c * 4;
                    bp[0] = v0; bp[1] = v1; bp[2] = v2; bp[3] = v3;
                }
            }
            __syncthreads();

            // ---- Phase 3a: forward replay, store alphas (pre-step, like ref) ----
            if (tid < NCH) {
                int c = tid;
                const float* bp = bndA + c * 4;
                float a0 = bp[0], a1 = bp[1], a2 = bp[2], a3 = bp[3];
                int base = c * CL;
                #pragma unroll 4
                for (int i = 0; i < CL; i++) {
                    int ts = SW(base + i);
                    alphas[ts] = make_float4(a0, a1, a2, a3);
                    float2 g = gpgm[ts];
                    float gp = g.x, gm = g.y;
                    float m0 = fmaxf(a0 - gp, a1 + gp);
                    float m2 = fmaxf(a0 + gp, a1 - gp);
                    float m1 = fmaxf(a2 + gm, a3 - gm);
                    float m3 = fmaxf(a2 - gm, a3 + gm);
                    a0 = m0; a1 = m1; a2 = m2; a3 = m3;
                }
            }
            __syncthreads();

            // ---- Phase 3b: backward replay + LLR + extrinsic scatter ----
            if (tid < NCH) {
                int c = tid;
                const float* bp = bndB + (c + 1) * 4;
                float b0 = bp[0], b1 = bp[1], b2 = bp[2], b3 = bp[3];
                int base = c * CL;
                #pragma unroll 2
                for (int i = CL - 1; i >= 0; i--) {
                    int t  = base + i;
                    int ts = SW(t);
                    float2 g = gpgm[ts];
                    float gp = g.x, gm = g.y;
                    float4 al = alphas[ts];
                    float t0p = b2 + gp, t1p = b0 + gp, t2p = b1 + gm, t3p = b3 + gm;
                    float t0m = b0 - gp, t1m = b2 - gp, t2m = b3 - gm, t3m = b1 - gm;
                    float m1v = fmaxf(fmaxf(al.x + t0p, al.y + t1p),
                                      fmaxf(al.z + t2p, al.w + t3p));
                    float m0v = fmaxf(fmaxf(al.x + t0m, al.y + t1m),
                                      fmaxf(al.z + t2m, al.w + t3m));
                    float llr = m1v - m0v;
                    b0 = fmaxf(t0m, t0p);
                    b1 = fmaxf(t1m, t1p);
                    b2 = fmaxf(t2m, t2p);
                    b3 = fmaxf(t3m, t3p);
                    if (dec == 0) {
                        // Le1 interleaved -> apriori of decoder 2
                        apri2[inv[t]] = llr - 2.0f * ys1[t] - apri1[t];
                    } else {
                        int il = ilv[t];
                        // Le2 deinterleaved -> apriori of decoder 1
                        apri1[il] = llr - 2.0f * ys1[il] - apri2[t];
                        if (it == NITER - 1) outr[il] = llr;  // final deinterleaved L2
                    }
                }
            }
            __syncthreads();
        }
    }
}

extern "C" void kernel_launch(void* const* d_in, const int* in_sizes, int n_in,
                              void* d_out, int out_size)
{
    const int*   x  = (const int*)d_in[0];
    const float* n1 = (const float*)d_in[1];
    const float* n2 = (const float*)d_in[2];
    const float* n3 = (const float*)d_in[3];
    const int*   il = (const int*)d_in[4];
    float* out = (float*)d_out;

    int B = in_sizes[0] / TK;

    cudaFuncSetAttribute(turbo_full_kernel,
                         cudaFuncAttributeMaxDynamicSharedMemorySize, SMEM_BYTES);
    turbo_full_kernel<<<B, NTHR, SMEM_BYTES>>>(x, n1, n2, n3, il, out);
}

// round 4
// speedup vs baseline: 2.4476x; 2.4451x over previous
#include <cuda_runtime.h>

#define TK    2048
#define SL    8          // sub-chunk length
#define NSUB  256        // number of sub-chunks
#define NCH   64         // chunks of 32 (4 subs)
#define NSUP  16         // supers of 128 (4 chunks)
#define NTHR  256
#define NITER 6
#define NEGV   (-1.0e4f)
#define NEGINF (-1.0e30f)

// XOR swizzles: bijections making stride-8 and stride-1 smem access conflict-free.
__device__ __forceinline__ int SW1(int t) { return t ^ ((t >> 5) & 31); }   // float arrays
__device__ __forceinline__ int SW2(int e) { return e ^ ((e >> 4) & 15); }   // float2 array

// ---- dynamic smem layout (bytes) ----
#define OFF_GPGM 0        // float2[2048]  16384
#define OFF_YS1  16384    // float[2048]    8192
#define OFF_YSI  24576    // float[2048]    8192  (ys1 interleaved)
#define OFF_YP2  32768    // float[2048]    8192
#define OFF_YP3  40960    // float[2048]    8192
#define OFF_AP1  49152    // float[2048]    8192
#define OFF_AP2  57344    // float[2048]    8192
#define OFF_MSUB 65536    // float[16][256] 16384 (SoA: [j*256+sub])
#define OFF_MCH  81920    // float[16][64]   4096
#define OFF_MSUP 86016    // float[16][16]   1024
#define OFF_BSA  87040    // float[17*4]      272
#define OFF_BSB  87312    // float[17*4]      272
#define OFF_BCA  87584    // float[65*4]     1040
#define OFF_BCB  88624    // float[65*4]     1040
#define OFF_ILV  89664    // u16[2048]       4096
#define OFF_INV  93760    // u16[2048]       4096
#define OFF_XB   97856    // u8[2048]        2048
#define OFF_EMAP 99904    // u8[128]
#define OFF_EST  100032   // u8[130]
#define SMEM_BYTES 100352

extern "C" __global__ void __launch_bounds__(NTHR, 2)
turbo_full_kernel(const int* __restrict__ x_g,
                  const float* __restrict__ n1_g,
                  const float* __restrict__ n2_g,
                  const float* __restrict__ n3_g,
                  const int* __restrict__ ilv_g,
                  float* __restrict__ out_g)
{
    extern __shared__ unsigned char sm[];
    float2* gpgm = (float2*)(sm + OFF_GPGM);
    float*  ys1  = (float*)(sm + OFF_YS1);
    float*  ysi  = (float*)(sm + OFF_YSI);
    float*  yp2  = (float*)(sm + OFF_YP2);
    float*  yp3  = (float*)(sm + OFF_YP3);
    float*  ap1  = (float*)(sm + OFF_AP1);
    float*  ap2  = (float*)(sm + OFF_AP2);
    float*  Msub = (float*)(sm + OFF_MSUB);
    float*  Mch  = (float*)(sm + OFF_MCH);
    float*  Msup = (float*)(sm + OFF_MSUP);
    float*  bSA  = (float*)(sm + OFF_BSA);
    float*  bSB  = (float*)(sm + OFF_BSB);
    float*  bCA  = (float*)(sm + OFF_BCA);
    float*  bCB  = (float*)(sm + OFF_BCB);
    unsigned short* ilv = (unsigned short*)(sm + OFF_ILV);
    unsigned short* inv = (unsigned short*)(sm + OFF_INV);
    unsigned char*  xb  = (unsigned char*)(sm + OFF_XB);
    unsigned char*  emap= (unsigned char*)(sm + OFF_EMAP);
    unsigned char*  est = (unsigned char*)(sm + OFF_EST);

    const int row = blockIdx.x;
    const int tid = threadIdx.x;

    const int*   xr  = x_g  + (size_t)row * TK;
    const float* n1r = n1_g + (size_t)row * TK;
    const float* n2r = n2_g + (size_t)row * TK;
    const float* n3r = n3_g + (size_t)row * TK;
    float*       outr= out_g+ (size_t)row * TK;

    // ---------------- Prologue ----------------
    for (int t = tid; t < TK; t += NTHR) {
        int il = ilv_g[t];
        ilv[SW1(t)] = (unsigned short)il;
        int u = xr[t];
        xb[t] = (unsigned char)u;
        int tw = SW1(t);
        ys1[tw] = (2.0f * (float)u - 1.0f) + n1r[t];
        yp2[tw] = n2r[t];
        yp3[tw] = n3r[t];
        ap1[tw] = 0.0f;
    }
    __syncthreads();
    for (int t = tid; t < TK; t += NTHR) {
        int il = ilv[SW1(t)];
        inv[SW1(il)] = (unsigned short)t;
        ysi[SW1(t)]  = ys1[SW1(il)];
    }

    // ---------------- Encoders (chunked state-map scan, 64 chunks of 32) --------
    if (tid < 128) {
        int e = tid >> 6, cc = tid & 63;
        unsigned m = 0xE4u;
        int base = cc * 32;
        for (int i = 0; i < 32; i++) {
            int t = base + i;
            unsigned u = e ? xb[ilv[SW1(t)]] : xb[t];
            unsigned nm = 0;
            #pragma unroll
            for (int k = 0; k < 4; k++) {
                unsigned s  = (m >> (2 * k)) & 3u;
                unsigned s1 = s >> 1, s2 = s & 1u;
                unsigned a  = u ^ s1 ^ s2;
                nm |= (((a << 1) | s1) << (2 * k));
            }
            m = nm;
        }
        emap[e * 64 + cc] = (unsigned char)m;
    }
    __syncthreads();
    if (tid == 0 || tid == 32) {
        int e = (tid == 32) ? 1 : 0;
        unsigned s = 0;
        for (int c = 0; c < 64; c++) {
            est[e * 65 + c] = (unsigned char)s;
            s = (emap[e * 64 + c] >> (2 * s)) & 3u;
        }
        est[e * 65 + 64] = (unsigned char)s;
    }
    __syncthreads();
    if (tid < 128) {
        int e = tid >> 6, cc = tid & 63;
        unsigned s = est[e * 65 + cc];
        int base = cc * 32;
        for (int i = 0; i < 32; i++) {
            int t = base + i;
            unsigned u  = e ? xb[ilv[SW1(t)]] : xb[t];
            unsigned s1 = s >> 1, s2 = s & 1u;
            unsigned a  = u ^ s1 ^ s2;
            unsigned p  = a ^ s2;
            float bp = 2.0f * (float)p - 1.0f;
            if (e) yp3[SW1(t)] += bp; else yp2[SW1(t)] += bp;
            s = (a << 1) | s1;
        }
    }
    __syncthreads();

    // ---------------- Turbo iterations ----------------
    for (int it = 0; it < NITER; it++) {
        for (int dec = 0; dec < 2; dec++) {
            const float* ysA = dec ? ysi : ys1;
            const float* apA = dec ? ap2 : ap1;
            const float* ypA = dec ? yp3 : yp2;

            // ---- Phase 1: gamma + per-sub-chunk forward 4x4 matrices ----
            {
                int sc = tid;
                float v00 = 0.0f,  v01 = NEGINF, v02 = NEGINF, v03 = NEGINF;
                float v10 = NEGINF,v11 = 0.0f,  v12 = NEGINF, v13 = NEGINF;
                float v20 = NEGINF,v21 = NEGINF,v22 = 0.0f,  v23 = NEGINF;
                float v30 = NEGINF,v31 = NEGINF,v32 = NEGINF,v33 = 0.0f;
                int base = sc * SL;
                #pragma unroll
                for (int i = 0; i < SL; i++) {
                    int t  = base + i;
                    int tw = SW1(t);
                    float a  = ysA[tw] + 0.5f * apA[tw];
                    float yp = ypA[tw];
                    float gp = a + yp, gm = a - yp;
                    gpgm[SW2(t)] = make_float2(gp, gm);
                    #define FWD4(A0,A1,A2,A3) { \
                        float _m0 = fmaxf(A0 - gp, A1 + gp); \
                        float _m2 = fmaxf(A0 + gp, A1 - gp); \
                        float _m1 = fmaxf(A2 + gm, A3 - gm); \
                        float _m3 = fmaxf(A2 - gm, A3 + gm); \
                        A0 = _m0; A1 = _m1; A2 = _m2; A3 = _m3; }
                    FWD4(v00, v01, v02, v03)
                    FWD4(v10, v11, v12, v13)
                    FWD4(v20, v21, v22, v23)
                    FWD4(v30, v31, v32, v33)
                    #undef FWD4
                }
                Msub[ 0*NSUB+sc]=v00; Msub[ 1*NSUB+sc]=v01; Msub[ 2*NSUB+sc]=v02; Msub[ 3*NSUB+sc]=v03;
                Msub[ 4*NSUB+sc]=v10; Msub[ 5*NSUB+sc]=v11; Msub[ 6*NSUB+sc]=v12; Msub[ 7*NSUB+sc]=v13;
                Msub[ 8*NSUB+sc]=v20; Msub[ 9*NSUB+sc]=v21; Msub[10*NSUB+sc]=v22; Msub[11*NSUB+sc]=v23;
                Msub[12*NSUB+sc]=v30; Msub[13*NSUB+sc]=v31; Msub[14*NSUB+sc]=v32; Msub[15*NSUB+sc]=v33;
            }
            __syncthreads();

            // ---- Phase 1b: compose 4 subs -> chunk matrices (row per thread) ----
            {
                int c = tid >> 2, r = tid & 3;
                const float* M0 = Msub + 4 * c;
                float w0 = M0[(r*4+0)*NSUB], w1 = M0[(r*4+1)*NSUB];
                float w2 = M0[(r*4+2)*NSUB], w3 = M0[(r*4+3)*NSUB];
                #pragma unroll
                for (int m = 1; m < 4; m++) {
                    const float* M = Msub + 4 * c + m;
                    float n0 = fmaxf(fmaxf(w0 + M[ 0*NSUB], w1 + M[ 4*NSUB]),
                                     fmaxf(w2 + M[ 8*NSUB], w3 + M[12*NSUB]));
                    float n1 = fmaxf(fmaxf(w0 + M[ 1*NSUB], w1 + M[ 5*NSUB]),
                                     fmaxf(w2 + M[ 9*NSUB], w3 + M[13*NSUB]));
                    float n2 = fmaxf(fmaxf(w0 + M[ 2*NSUB], w1 + M[ 6*NSUB]),
                                     fmaxf(w2 + M[10*NSUB], w3 + M[14*NSUB]));
                    float n3 = fmaxf(fmaxf(w0 + M[ 3*NSUB], w1 + M[ 7*NSUB]),
                                     fmaxf(w2 + M[11*NSUB], w3 + M[15*NSUB]));
                    w0 = n0; w1 = n1; w2 = n2; w3 = n3;
                }
                Mch[(r*4+0)*NCH + c] = w0; Mch[(r*4+1)*NCH + c] = w1;
                Mch[(r*4+2)*NCH + c] = w2; Mch[(r*4+3)*NCH + c] = w3;
            }
            __syncthreads();

            // ---- Phase 1c: compose 4 chunks -> super matrices ----
            if (tid < 64) {
                int p = tid >> 2, r = tid & 3;
                const float* M0 = Mch + 4 * p;
                float w0 = M0[(r*4+0)*NCH], w1 = M0[(r*4+1)*NCH];
                float w2 = M0[(r*4+2)*NCH], w3 = M0[(r*4+3)*NCH];
                #pragma unroll
                for (int m = 1; m < 4; m++) {
                    const float* M = Mch + 4 * p + m;
                    float n0 = fmaxf(fmaxf(w0 + M[ 0*NCH], w1 + M[ 4*NCH]),
                                     fmaxf(w2 + M[ 8*NCH], w3 + M[12*NCH]));
                    float n1 = fmaxf(fmaxf(w0 + M[ 1*NCH], w1 + M[ 5*NCH]),
                                     fmaxf(w2 + M[ 9*NCH], w3 + M[13*NCH]));
                    float n2 = fmaxf(fmaxf(w0 + M[ 2*NCH], w1 + M[ 6*NCH]),
                                     fmaxf(w2 + M[10*NCH], w3 + M[14*NCH]));
                    float n3 = fmaxf(fmaxf(w0 + M[ 3*NCH], w1 + M[ 7*NCH]),
                                     fmaxf(w2 + M[11*NCH], w3 + M[15*NCH]));
                    w0 = n0; w1 = n1; w2 = n2; w3 = n3;
                }
                Msup[(r*4+0)*NSUP + p] = w0; Msup[(r*4+1)*NSUP + p] = w1;
                Msup[(r*4+2)*NSUP + p] = w2; Msup[(r*4+3)*NSUP + p] = w3;
            }
            __syncthreads();

            // ---- Phase 2: serial scans over 16 super matrices (2 warps) ----
            if (tid == 0) {
                float v0 = 0.0f, v1 = NEGV, v2 = NEGV, v3 = NEGV;
                bSA[0] = v0; bSA[1] = v1; bSA[2] = v2; bSA[3] = v3;
                for (int p = 0; p < NSUP; p++) {
                    const float* M = Msup + p;
                    float s  = v0 + M[0];   // off-chain normalizer (<= w0)
                    float w0 = fmaxf(fmaxf(v0 + M[ 0*NSUP], v1 + M[ 4*NSUP]),
                                     fmaxf(v2 + M[ 8*NSUP], v3 + M[12*NSUP]));
                    float w1 = fmaxf(fmaxf(v0 + M[ 1*NSUP], v1 + M[ 5*NSUP]),
                                     fmaxf(v2 + M[ 9*NSUP], v3 + M[13*NSUP]));
                    float w2 = fmaxf(fmaxf(v0 + M[ 2*NSUP], v1 + M[ 6*NSUP]),
                                     fmaxf(v2 + M[10*NSUP], v3 + M[14*NSUP]));
                    float w3 = fmaxf(fmaxf(v0 + M[ 3*NSUP], v1 + M[ 7*NSUP]),
                                     fmaxf(v2 + M[11*NSUP], v3 + M[15*NSUP]));
                    v0 = w0 - s; v1 = w1 - s; v2 = w2 - s; v3 = w3 - s;
                    float* bp = bSA + (p + 1) * 4;
                    bp[0] = v0; bp[1] = v1; bp[2] = v2; bp[3] = v3;
                }
            } else if (tid == 32) {
                float v0 = 0.0f, v1 = 0.0f, v2 = 0.0f, v3 = 0.0f;
                float* be = bSB + NSUP * 4;
                be[0] = 0.0f; be[1] = 0.0f; be[2] = 0.0f; be[3] = 0.0f;
                for (int p = NSUP - 1; p >= 0; p--) {
                    const float* M = Msup + p;
                    float s  = v0 + M[0];
                    float w0 = fmaxf(fmaxf(M[ 0*NSUP] + v0, M[ 1*NSUP] + v1),
                                     fmaxf(M[ 2*NSUP] + v2, M[ 3*NSUP] + v3));
                    float w1 = fmaxf(fmaxf(M[ 4*NSUP] + v0, M[ 5*NSUP] + v1),
                                     fmaxf(M[ 6*NSUP] + v2, M[ 7*NSUP] + v3));
                    float w2 = fmaxf(fmaxf(M[ 8*NSUP] + v0, M[ 9*NSUP] + v1),
                                     fmaxf(M[10*NSUP] + v2, M[11*NSUP] + v3));
                    float w3 = fmaxf(fmaxf(M[12*NSUP] + v0, M[13*NSUP] + v1),
                                     fmaxf(M[14*NSUP] + v2, M[15*NSUP] + v3));
                    v0 = w0 - s; v1 = w1 - s; v2 = w2 - s; v3 = w3 - s;
                    float* bp = bSB + p * 4;
                    bp[0] = v0; bp[1] = v1; bp[2] = v2; bp[3] = v3;
                }
            }
            __syncthreads();

            // ---- Phase 2b: super -> chunk boundaries (32 parallel threads) ----
            if (tid < 16) {
                int p = tid;
                float v0 = bSA[p*4+0], v1 = bSA[p*4+1], v2 = bSA[p*4+2], v3 = bSA[p*4+3];
                float* bp0 = bCA + (4*p) * 4;
                bp0[0] = v0; bp0[1] = v1; bp0[2] = v2; bp0[3] = v3;
                #pragma unroll
                for (int cl = 0; cl < 3; cl++) {
                    int c = 4*p + cl;
                    const float* M = Mch + c;
                    float s  = v0 + M[0];
                    float w0 = fmaxf(fmaxf(v0 + M[ 0*NCH], v1 + M[ 4*NCH]),
                                     fmaxf(v2 + M[ 8*NCH], v3 + M[12*NCH]));
                    float w1 = fmaxf(fmaxf(v0 + M[ 1*NCH], v1 + M[ 5*NCH]),
                                     fmaxf(v2 + M[ 9*NCH], v3 + M[13*NCH]));
                    float w2 = fmaxf(fmaxf(v0 + M[ 2*NCH], v1 + M[ 6*NCH]),
                                     fmaxf(v2 + M[10*NCH], v3 + M[14*NCH]));
                    float w3 = fmaxf(fmaxf(v0 + M[ 3*NCH], v1 + M[ 7*NCH]),
                                     fmaxf(v2 + M[11*NCH], v3 + M[15*NCH]));
                    v0 = w0 - s; v1 = w1 - s; v2 = w2 - s; v3 = w3 - s;
                    float* bp = bCA + (c + 1) * 4;
                    bp[0] = v0; bp[1] = v1; bp[2] = v2; bp[3] = v3;
                }
            } else if (tid >= 32 && tid < 48) {
                int p = tid - 32;
                float v0 = bSB[(p+1)*4+0], v1 = bSB[(p+1)*4+1];
                float v2 = bSB[(p+1)*4+2], v3 = bSB[(p+1)*4+3];
                float* bp4 = bCB + (4*p + 4) * 4;
                bp4[0] = v0; bp4[1] = v1; bp4[2] = v2; bp4[3] = v3;
                #pragma unroll
                for (int cl = 3; cl >= 1; cl--) {
                    int c = 4*p + cl;
                    const float* M = Mch + c;
                    float s  = v0 + M[0];
                    float w0 = fmaxf(fmaxf(M[ 0*NCH] + v0, M[ 1*NCH] + v1),
                                     fmaxf(M[ 2*NCH] + v2, M[ 3*NCH] + v3));
                    float w1 = fmaxf(fmaxf(M[ 4*NCH] + v0, M[ 5*NCH] + v1),
                                     fmaxf(M[ 6*NCH] + v2, M[ 7*NCH] + v3));
                    float w2 = fmaxf(fmaxf(M[ 8*NCH] + v0, M[ 9*NCH] + v1),
                                     fmaxf(M[10*NCH] + v2, M[11*NCH] + v3));
                    float w3 = fmaxf(fmaxf(M[12*NCH] + v0, M[13*NCH] + v1),
                                     fmaxf(M[14*NCH] + v2, M[15*NCH] + v3));
                    v0 = w0 - s; v1 = w1 - s; v2 = w2 - s; v3 = w3 - s;
                    float* bp = bCB + c * 4;
                    bp[0] = v0; bp[1] = v1; bp[2] = v2; bp[3] = v3;
                }
            }
            __syncthreads();

            // ---- Phase 3: per-sub-chunk fwd walk (alphas in regs) + bwd/LLR ----
            {
                int sc = tid, c = sc >> 2, kk = sc & 3;
                // alpha at sub-chunk entry: chunk boundary + <=3 sub-matrix matvecs
                float a0 = bCA[c*4+0], a1 = bCA[c*4+1], a2 = bCA[c*4+2], a3 = bCA[c*4+3];
                #pragma unroll
                for (int m = 0; m < 3; m++) {
                    if (m < kk) {
                        const float* M = Msub + 4*c + m;
                        float n0 = fmaxf(fmaxf(a0 + M[ 0*NSUB], a1 + M[ 4*NSUB]),
                                         fmaxf(a2 + M[ 8*NSUB], a3 + M[12*NSUB]));
                        float n1 = fmaxf(fmaxf(a0 + M[ 1*NSUB], a1 + M[ 5*NSUB]),
                                         fmaxf(a2 + M[ 9*NSUB], a3 + M[13*NSUB]));
                        float n2 = fmaxf(fmaxf(a0 + M[ 2*NSUB], a1 + M[ 6*NSUB]),
                                         fmaxf(a2 + M[10*NSUB], a3 + M[14*NSUB]));
                        float n3 = fmaxf(fmaxf(a0 + M[ 3*NSUB], a1 + M[ 7*NSUB]),
                                         fmaxf(a2 + M[11*NSUB], a3 + M[15*NSUB]));
                        a0 = n0; a1 = n1; a2 = n2; a3 = n3;
                    }
                }
                // beta at sub-chunk exit: next chunk boundary back through subs kk+1..3
                float b0 = bCB[(c+1)*4+0], b1 = bCB[(c+1)*4+1];
                float b2 = bCB[(c+1)*4+2], b3 = bCB[(c+1)*4+3];
                #pragma unroll
                for (int m = 3; m >= 1; m--) {
                    if (m > kk) {
                        const float* M = Msub + 4*c + m;
                        float n0 = fmaxf(fmaxf(M[ 0*NSUB] + b0, M[ 1*NSUB] + b1),
                                         fmaxf(M[ 2*NSUB] + b2, M[ 3*NSUB] + b3));
                        float n1 = fmaxf(fmaxf(M[ 4*NSUB] + b0, M[ 5*NSUB] + b1),
                                         fmaxf(M[ 6*NSUB] + b2, M[ 7*NSUB] + b3));
                        float n2 = fmaxf(fmaxf(M[ 8*NSUB] + b0, M[ 9*NSUB] + b1),
                                         fmaxf(M[10*NSUB] + b2, M[11*NSUB] + b3));
                        float n3 = fmaxf(fmaxf(M[12*NSUB] + b0, M[13*NSUB] + b1),
                                         fmaxf(M[14*NSUB] + b2, M[15*NSUB] + b3));
                        b0 = n0; b1 = n1; b2 = n2; b3 = n3;
                    }
                }
                // forward walk: keep pre-step alphas and gammas in registers
                float A0[SL], A1[SL], A2[SL], A3[SL], GP[SL], GM[SL];
                int base = sc * SL;
                #pragma unroll
                for (int i = 0; i < SL; i++) {
                    float2 g = gpgm[SW2(base + i)];
                    GP[i] = g.x; GM[i] = g.y;
                    A0[i] = a0; A1[i] = a1; A2[i] = a2; A3[i] = a3;
                    float m0 = fmaxf(a0 - g.x, a1 + g.x);
                    float m2 = fmaxf(a0 + g.x, a1 - g.x);
                    float m1 = fmaxf(a2 + g.y, a3 - g.y);
                    float m3 = fmaxf(a2 - g.y, a3 + g.y);
                    a0 = m0; a1 = m1; a2 = m2; a3 = m3;
                }
                // backward walk: beta update + LLR + extrinsic scatter
                const unsigned short* dst = dec ? ilv : inv;
                const bool lastout = (dec == 1) && (it == NITER - 1);
                #pragma unroll
                for (int i = SL - 1; i >= 0; i--) {
                    float gp = GP[i], gm = GM[i];
                    float t0p = b2 + gp, t1p = b0 + gp, t2p = b1 + gm, t3p = b3 + gm;
                    float t0m = b0 - gp, t1m = b2 - gp, t2m = b3 - gm, t3m = b1 - gm;
                    float m1v = fmaxf(fmaxf(A0[i] + t0p, A1[i] + t1p),
                                      fmaxf(A2[i] + t2p, A3[i] + t3p));
                    float m0v = fmaxf(fmaxf(A0[i] + t0m, A1[i] + t1m),
                                      fmaxf(A2[i] + t2m, A3[i] + t3m));
                    float llr = m1v - m0v;
                    b0 = fmaxf(t0m, t0p); b1 = fmaxf(t1m, t1p);
                    b2 = fmaxf(t2m, t2p); b3 = fmaxf(t3m, t3p);
                    int t = base + i;
                    int dv = dst[SW1(t)];
                    float ex = llr - (gp + gm);   // llr - 2*ys - La  (gp+gm == 2*ys+La)
                    if (dec == 0) {
                        ap2[SW1(dv)] = ex;
                    } else {
                        ap1[SW1(dv)] = ex;
                        if (lastout) outr[dv] = llr;
                    }
                }
            }
            __syncthreads();
        }
    }
}

extern "C" void kernel_launch(void* const* d_in, const int* in_sizes, int n_in,
                              void* d_out, int out_size)
{
    const int*   x  = (const int*)d_in[0];
    const float* n1 = (const float*)d_in[1];
    const float* n2 = (const float*)d_in[2];
    const float* n3 = (const float*)d_in[3];
    const int*   il = (const int*)d_in[4];
    float* out = (float*)d_out;

    int B = in_sizes[0] / TK;

    cudaFuncSetAttribute(turbo_full_kernel,
                         cudaFuncAttributeMaxDynamicSharedMemorySize, SMEM_BYTES);
    turbo_full_kernel<<<B, NTHR, SMEM_BYTES>>>(x, n1, n2, n3, il, out);
}